// round 3
// baseline (speedup 1.0000x reference)
#include <cuda_runtime.h>
#include <cstdint>

// Problem constants
#define B_DIM   128
#define OUT_DIM 1024
#define IN_DIM  1024

// Scratch: s[o,k] = d + a * sigmoid(dx * (w - x0))  (4 MB, static device array)
__device__ float g_sig[OUT_DIM * IN_DIM];

// ---------------------------------------------------------------------------
// Pipe-steering helpers. `one` is a runtime kernel argument equal to 1; ptxas
// cannot constant-fold it, so mad.lo.u32 with multiplier `one` stays an IMAD
// on the fma pipe instead of an IADD3 on the (saturated) alu pipe.
// ---------------------------------------------------------------------------
__device__ __forceinline__ uint32_t imad(uint32_t a, uint32_t b, uint32_t c) {
    uint32_t r;
    asm("mad.lo.u32 %0, %1, %2, %3;" : "=r"(r) : "r"(a), "r"(b), "r"(c));
    return r;
}
__device__ __forceinline__ uint32_t imul_lo(uint32_t a, uint32_t b) {
    uint32_t r;
    asm("mul.lo.u32 %0, %1, %2;" : "=r"(r) : "r"(a), "r"(b));
    return r;
}
__device__ __forceinline__ uint32_t imul_hi(uint32_t a, uint32_t b) {
    uint32_t r;
    asm("mul.hi.u32 %0, %1, %2;" : "=r"(r) : "r"(a), "r"(b));
    return r;
}
__device__ __forceinline__ uint32_t rotl32(uint32_t x, int r) {
    return __funnelshift_l(x, x, r);
}

// ---------------------------------------------------------------------------
// threefry2x32, key = (0, 42); partitionable random_bits:
//   ctr = (0, i), bits = out0 ^ out1.
// Round adds + key injections forced to IMAD (fma pipe). Rotates for the
// three r=26 rounds and the first r=15 round are done as mul.lo/mul.hi pairs
// (fma pipe) with the OR fused into the following LOP3 xor (alu pipe).
// ---------------------------------------------------------------------------
__device__ __forceinline__ uint32_t threefry_bits_42(uint32_t i, uint32_t one,
                                                     uint32_t m15, uint32_t m26) {
    const uint32_t ks1 = 42u, ks2 = 0x1BD11BF0u;

    uint32_t x1 = i + ks1;
    uint32_t x0 = x1;                 // round 1 add with x0_init = 0 folded
    x1 = rotl32(x1, 13) ^ x0;         // round 1 (r=13)

    // round 2 (r=15) — fma-pipe rotate
    x0 = imad(x1, one, x0);
    { uint32_t lo = imul_lo(x1, m15), hi = imul_hi(x1, m15); x1 = (lo | hi) ^ x0; }

    // round 3 (r=26) — fma-pipe rotate
    x0 = imad(x1, one, x0);
    { uint32_t lo = imul_lo(x1, m26), hi = imul_hi(x1, m26); x1 = (lo | hi) ^ x0; }

    // round 4 (r=6)
    x0 = imad(x1, one, x0);  x1 = rotl32(x1, 6) ^ x0;

    // inject 1
    x0 = imad(ks1, one, x0);
    x1 = imad(ks2 + 1u, one, x1);

    x0 = imad(x1, one, x0);  x1 = rotl32(x1, 17) ^ x0;
    x0 = imad(x1, one, x0);  x1 = rotl32(x1, 29) ^ x0;
    x0 = imad(x1, one, x0);  x1 = rotl32(x1, 16) ^ x0;
    x0 = imad(x1, one, x0);  x1 = rotl32(x1, 24) ^ x0;

    // inject 2
    x0 = imad(ks2, one, x0);
    x1 = imad(2u, one, x1);

    x0 = imad(x1, one, x0);  x1 = rotl32(x1, 13) ^ x0;
    x0 = imad(x1, one, x0);  x1 = rotl32(x1, 15) ^ x0;
    // round 11 (r=26) — fma-pipe rotate
    x0 = imad(x1, one, x0);
    { uint32_t lo = imul_lo(x1, m26), hi = imul_hi(x1, m26); x1 = (lo | hi) ^ x0; }
    x0 = imad(x1, one, x0);  x1 = rotl32(x1, 6) ^ x0;

    // inject 3
    x0 = imad(0u, one, x0);              // +ks0 = 0 (folds away)
    x1 = imad(ks1 + 3u, one, x1);

    x0 = imad(x1, one, x0);  x1 = rotl32(x1, 17) ^ x0;
    x0 = imad(x1, one, x0);  x1 = rotl32(x1, 29) ^ x0;
    x0 = imad(x1, one, x0);  x1 = rotl32(x1, 16) ^ x0;
    x0 = imad(x1, one, x0);  x1 = rotl32(x1, 24) ^ x0;

    // inject 4
    x0 = imad(ks1, one, x0);
    x1 = imad(ks2 + 4u, one, x1);

    x0 = imad(x1, one, x0);  x1 = rotl32(x1, 13) ^ x0;
    x0 = imad(x1, one, x0);  x1 = rotl32(x1, 15) ^ x0;
    // round 19 (r=26) — fma-pipe rotate
    x0 = imad(x1, one, x0);
    { uint32_t lo = imul_lo(x1, m26), hi = imul_hi(x1, m26); x1 = (lo | hi) ^ x0; }
    x0 = imad(x1, one, x0);  x1 = rotl32(x1, 6) ^ x0;

    // inject 5
    x0 = imad(ks2, one, x0);
    x1 = imad(5u, one, x1);

    return x0 ^ x1;
}

// ---------------------------------------------------------------------------
// Kernel 1: precompute s[o,k] = d + a * sigmoid(dx * (w - x0))
// ---------------------------------------------------------------------------
__global__ void sls_sigmoid_kernel(const float* __restrict__ w,
                                   const float* __restrict__ x0,
                                   const float* __restrict__ dx,
                                   const float* __restrict__ a,
                                   const float* __restrict__ d) {
    int i = blockIdx.x * blockDim.x + threadIdx.x;
    if (i < OUT_DIM * IN_DIM) {
        float z  = dx[i] * (w[i] - x0[i]);
        float sg = 1.0f / (1.0f + expf(-z));
        g_sig[i] = d[i] + a[i] * sg;
    }
}

// ---------------------------------------------------------------------------
// Kernel 2: one warp per (b, o); each lane processes 8 float4 chunks
// (32 k-values). out[b,o] = count{ u < p } + bias[o].
// Compare: bitcast((bits>>9) + 0x3f800000) < fma(in, s, 1.0f)
//   (u = v - 1 exactly; clamp is a data no-op since in,s in [0,1)).
// ---------------------------------------------------------------------------
__global__ void __launch_bounds__(256)
sls_main_kernel(const float* __restrict__ input,
                const float* __restrict__ bias,
                float* __restrict__ out,
                uint32_t one) {
    int gtid = blockIdx.x * blockDim.x + threadIdx.x;
    int w    = gtid >> 5;            // warp id: 0 .. 128*1024-1
    int lane = gtid & 31;

    int o = w & (OUT_DIM - 1);       // 0..1023
    int b = w >> 10;                 // 0..127

    const float4* __restrict__ s4 = (const float4*)(g_sig + o * IN_DIM);
    const float4* __restrict__ i4 = (const float4*)(input + b * IN_DIM);

    const uint32_t m15 = one << 15;
    const uint32_t m26 = one << 26;
    const uint32_t expo = imul_lo(one, 0x3f800000u);  // keep in reg, opaque

    // flattened element index base for this thread's e=0 of chunk j:
    // i = b*2^20 + o*2^10 + (j*128 + lane*4 + e)
    uint32_t tbase = ((uint32_t)b << 20) + ((uint32_t)o << 10) + ((uint32_t)lane << 2);

    int cnt = 0;

#pragma unroll 1
    for (int j = 0; j < 8; j++) {
        int idx = (j << 5) + lane;       // float4 index, coalesced
        float4 iv = i4[idx];
        float4 sv = s4[idx];
        uint32_t c = tbase + ((uint32_t)j << 7);

        {
            uint32_t bits = threefry_bits_42(c + 0u, one, m15, m26);
            float v = __uint_as_float(imad(bits >> 9, one, expo));
            cnt += (v < __fmaf_rn(iv.x, sv.x, 1.0f)) ? 1 : 0;
        }
        {
            uint32_t bits = threefry_bits_42(c + 1u, one, m15, m26);
            float v = __uint_as_float(imad(bits >> 9, one, expo));
            cnt += (v < __fmaf_rn(iv.y, sv.y, 1.0f)) ? 1 : 0;
        }
        {
            uint32_t bits = threefry_bits_42(c + 2u, one, m15, m26);
            float v = __uint_as_float(imad(bits >> 9, one, expo));
            cnt += (v < __fmaf_rn(iv.z, sv.z, 1.0f)) ? 1 : 0;
        }
        {
            uint32_t bits = threefry_bits_42(c + 3u, one, m15, m26);
            float v = __uint_as_float(imad(bits >> 9, one, expo));
            cnt += (v < __fmaf_rn(iv.w, sv.w, 1.0f)) ? 1 : 0;
        }
    }

    cnt = __reduce_add_sync(0xffffffffu, cnt);

    if (lane == 0) {
        out[b * OUT_DIM + o] = (float)cnt + bias[o];
    }
}

// ---------------------------------------------------------------------------
// kernel_launch
// Inputs (metadata order): input(128*1024), weight(1024*1024), bias(1024),
//                          x0, dx, a, d (each 1024*1024)
// Output: (128, 1024) float32
// ---------------------------------------------------------------------------
extern "C" void kernel_launch(void* const* d_in, const int* in_sizes, int n_in,
                              void* d_out, int out_size) {
    const float* input  = (const float*)d_in[0];
    const float* weight = (const float*)d_in[1];
    const float* bias   = (const float*)d_in[2];
    const float* x0     = (const float*)d_in[3];
    const float* dx     = (const float*)d_in[4];
    const float* a      = (const float*)d_in[5];
    const float* d      = (const float*)d_in[6];
    float* out          = (float*)d_out;

    // Kernel 1: sigmoid table (1M elements)
    {
        int threads = 256;
        int blocks  = (OUT_DIM * IN_DIM + threads - 1) / threads;
        sls_sigmoid_kernel<<<blocks, threads>>>(weight, x0, dx, a, d);
    }

    // Kernel 2: 128*1024 warps, 8 warps/block -> 16384 blocks
    {
        int threads = 256;
        int blocks  = (B_DIM * OUT_DIM * 32) / threads;  // 16384
        sls_main_kernel<<<blocks, threads>>>(input, bias, out, 1u);
    }
}